// round 12
// baseline (speedup 1.0000x reference)
#include <cuda_runtime.h>
#include <cuda_fp16.h>
#include <cstdint>

// Problem constants
#define B      8
#define C_IN   16
#define H      128
#define W      128
#define KSIZE  3
#define HO     126
#define WO     126
#define NK     128

#define TILE_X 32
#define TILE_Y 16
#define NTHREADS 512

// Weights fp16, layout [k][t][c]: half index = k*152 + t*16 + c
// per-k stride 304 B = 19 quads (odd -> random k spreads over 8 bank-quads)
#define WKH     152
#define W_TOTAL_H (NK * WKH)                 // 19456 halves
#define W_BYTES   (W_TOTAL_H * 2)            // 38912

// Data records fp16 in smem: [p][c], p = ry*DIN_X+rx, record 32 B, stride 48 B
#define DIN_Y   (TILE_Y + KSIZE - 1)         // 18
#define DIN_X   (TILE_X + KSIZE - 1)         // 34
#define NREC    (DIN_Y * DIN_X)              // 612
#define RECSTR  48
#define D_BYTES (NREC * RECSTR)              // 29376
#define D_OFF   W_BYTES

#define SMEM_BYTES (W_BYTES + D_BYTES)       // 68288 (x2 blocks = 136.6 KB/SM)

__device__ __align__(16) __half g_wbuf[W_TOTAL_H];
__device__ __align__(16) __half g_dbuf[B * H * W * C_IN];   // [b][h][w][c]

// ---------- cp.async helpers ----------
__device__ __forceinline__ void cp_async16(unsigned int dst, const void* src) {
    asm volatile("cp.async.cg.shared.global [%0], [%1], 16;\n" :: "r"(dst), "l"(src));
}
__device__ __forceinline__ void cp_async_wait_all() {
    asm volatile("cp.async.commit_group;\n");
    asm volatile("cp.async.wait_group 0;\n" ::: "memory");
}

// ---------- prep: weights -> g_wbuf [k][t][c] ; data -> g_dbuf [b][h][w][c] ----------
#define WPREP_BLOCKS 36
__global__ void prep_kernel(const float* __restrict__ weights,
                            const float* __restrict__ data)
{
    const int tid = threadIdx.x;                  // 128 threads
    if (blockIdx.x < WPREP_BLOCKS) {
        int i4 = blockIdx.x * 128 + tid;
        if (i4 >= (NK * C_IN * 9) / 4) return;    // 4608 float4s
        float4 v = reinterpret_cast<const float4*>(weights)[i4];
        int base = i4 * 4;
        #pragma unroll
        for (int u = 0; u < 4; ++u) {
            int e = base + u;
            int k = e / 144;
            int r = e - k * 144;
            int c = r / 9;
            int t = r - c * 9;
            float f = (u == 0) ? v.x : (u == 1) ? v.y : (u == 2) ? v.z : v.w;
            g_wbuf[k * WKH + t * 16 + c] = __float2half_rn(f);
        }
    } else {
        // one block per (b, h); thread = w. Coalesced reads per c, 32B/thread writes.
        int idx = blockIdx.x - WPREP_BLOCKS;      // 0..1023
        int b = idx >> 7;
        int h = idx & 127;
        int w = tid;
        const float* src = data + ((size_t)(b * C_IN) * H + h) * W + w;  // + c*H*W
        unsigned hh[8];
        #pragma unroll
        for (int c2 = 0; c2 < 8; ++c2) {
            float f0 = src[(2 * c2 + 0) * H * W];
            float f1 = src[(2 * c2 + 1) * H * W];
            __half2 p = __floats2half2_rn(f0, f1);
            hh[c2] = *reinterpret_cast<unsigned*>(&p);
        }
        uint4* dst = reinterpret_cast<uint4*>(g_dbuf + ((size_t)(b * H + h) * W + w) * C_IN);
        uint4 q0; q0.x = hh[0]; q0.y = hh[1]; q0.z = hh[2]; q0.w = hh[3];
        uint4 q1; q1.x = hh[4]; q1.y = hh[5]; q1.z = hh[6]; q1.w = hh[7];
        dst[0] = q0;
        dst[1] = q1;
    }
}

// ---------- main ----------
__global__ __launch_bounds__(NTHREADS, 2)
void kernel_lookup_kernel(const int* __restrict__ kernel_idx,
                          float* __restrict__ out)
{
    extern __shared__ __align__(16) char smem[];
    const unsigned int smem_u32 = (unsigned int)__cvta_generic_to_shared(smem);

    const int tid = threadIdx.x;
    const int b   = blockIdx.z;
    const int ty0 = blockIdx.y * TILE_Y;
    const int tx0 = blockIdx.x * TILE_X;

    const int tx = tid & 31;
    const int ty = tid >> 5;            // 0..15
    const int oy = ty0 + ty;
    const int ox = tx0 + tx;
    const bool valid = (oy < HO) && (ox < WO);

    int k = 0;
    if (valid) k = kernel_idx[((size_t)b * HO + oy) * WO + ox];

    // ---- stage weights: coalesced 16B async copies ----
    {
        const char* src = reinterpret_cast<const char*>(g_wbuf);
        #pragma unroll 1
        for (int i = tid; i < W_BYTES / 16; i += NTHREADS)       // 2432
            cp_async16(smem_u32 + i * 16, src + i * 16);
    }

    // ---- stage data records: 32B contiguous gmem -> 48B-strided smem ----
    {
        const __half* dimg = g_dbuf + (size_t)b * H * W * C_IN;
        #pragma unroll 1
        for (int p = tid; p < NREC; p += NTHREADS) {             // 612 records
            int ry = p / DIN_X;
            int rx = p - ry * DIN_X;
            int gy = ty0 + ry;
            int gx = tx0 + rx;
            if (gy >= H || gx >= W) continue;   // garbage only feeds invalid px
            const char* src = reinterpret_cast<const char*>(dimg + ((size_t)gy * W + gx) * C_IN);
            unsigned int dst = smem_u32 + D_OFF + p * RECSTR;
            cp_async16(dst,      src);
            cp_async16(dst + 16, src + 16);
        }
    }

    cp_async_wait_all();
    __syncthreads();

    // ---- compute: 2-stage software pipeline over the 9 taps ----
    const uint4* wq    = reinterpret_cast<const uint4*>(smem + k * (WKH * 2));   // 19 quads/k
    const char*  dbase = smem + D_OFF + (ty * DIN_X + tx) * RECSTR;

    const int doff[9] = { 0*RECSTR, 1*RECSTR, 2*RECSTR,
                          34*RECSTR, 35*RECSTR, 36*RECSTR,
                          68*RECSTR, 69*RECSTR, 70*RECSTR };

    float acc0 = 0.f, acc1 = 0.f, acc2 = 0.f, acc3 = 0.f;

    uint4 wA = wq[0], wB = wq[1];
    uint4 dA = reinterpret_cast<const uint4*>(dbase)[0];
    uint4 dB = reinterpret_cast<const uint4*>(dbase)[1];

    #pragma unroll
    for (int t = 0; t < 9; ++t) {
        uint4 wA_n, wB_n, dA_n, dB_n;
        if (t < 8) {
            wA_n = wq[(t + 1) * 2];
            wB_n = wq[(t + 1) * 2 + 1];
            const uint4* dq = reinterpret_cast<const uint4*>(dbase + doff[t + 1]);
            dA_n = dq[0];
            dB_n = dq[1];
        }

        const unsigned* wa = &wA.x;
        const unsigned* da = &dA.x;
        #pragma unroll
        for (int j = 0; j < 4; ++j) {
            float2 wf = __half22float2(*reinterpret_cast<const __half2*>(&wa[j]));
            float2 df = __half22float2(*reinterpret_cast<const __half2*>(&da[j]));
            acc0 = fmaf(wf.x, df.x, acc0);
            acc1 = fmaf(wf.y, df.y, acc1);
        }
        const unsigned* wb = &wB.x;
        const unsigned* db = &dB.x;
        #pragma unroll
        for (int j = 0; j < 4; ++j) {
            float2 wf = __half22float2(*reinterpret_cast<const __half2*>(&wb[j]));
            float2 df = __half22float2(*reinterpret_cast<const __half2*>(&db[j]));
            acc2 = fmaf(wf.x, df.x, acc2);
            acc3 = fmaf(wf.y, df.y, acc3);
        }

        wA = wA_n; wB = wB_n; dA = dA_n; dB = dB_n;
    }

    if (valid)
        out[((size_t)b * HO + oy) * WO + ox] = (acc0 + acc1) + (acc2 + acc3);
}

extern "C" void kernel_launch(void* const* d_in, const int* in_sizes, int n_in,
                              void* d_out, int out_size)
{
    const float* data = (const float*)d_in[0];
    const int*   kidx = (const int*)d_in[1];
    const float* wts  = (const float*)d_in[2];
    float*       outp = (float*)d_out;

    prep_kernel<<<WPREP_BLOCKS + B * H, 128>>>(wts, data);   // weights + data transpose

    cudaFuncSetAttribute(kernel_lookup_kernel,
                         cudaFuncAttributeMaxDynamicSharedMemorySize,
                         SMEM_BYTES);
    dim3 grid((WO + TILE_X - 1) / TILE_X,      // 4
              (HO + TILE_Y - 1) / TILE_Y,      // 8
              B);                               // 8 -> 256 blocks, 2/SM
    kernel_lookup_kernel<<<grid, NTHREADS, SMEM_BYTES>>>(kidx, outp);
}